// round 14
// baseline (speedup 1.0000x reference)
#include <cuda_runtime.h>
#include <math.h>

#define PACK_BLOCKS 1184
#define MAIN_BLOCKS 888
#define THREADS 256
#define MAXN 8192
#define MAXWPR (MAXN / 32)

__device__ unsigned g_bits[(size_t)MAXN * MAXWPR];   // 8 MB packed upper-tri mask
// [0] peri accumulator (double bits), [1] done counter, [2] quad ticket
__device__ unsigned long long g_state[3];
__device__ float g_r, g_gtr, g_gtperi;

__device__ __forceinline__ float fsqrt_fast(float x) {
    float r;
    asm("sqrt.approx.f32 %0, %1;" : "=f"(r) : "f"(x));
    return r;
}

__device__ __forceinline__ float block_sum256(float v, float* sh) {
    const int t = threadIdx.x;
    for (int o = 16; o > 0; o >>= 1)
        v += __shfl_down_sync(0xffffffffu, v, o);
    if ((t & 31) == 0) sh[t >> 5] = v;
    __syncthreads();
    float r = 0.f;
    if (t < 32) {
        r = (t < 8) ? sh[t] : 0.f;
        for (int o = 4; o > 0; o >>= 1)
            r += __shfl_down_sync(0xffffffffu, r, o);
        if (t == 0) sh[0] = r;
    }
    __syncthreads();
    r = sh[0];
    __syncthreads();
    return r;
}

// ---------------------------------------------------------------------------
// pack_kernel: pure streaming read of A's upper triangle -> bit matrix.
// One warp handles a group of 4 words (128 columns) of one row per iteration.
// Bits with col <= row are forced to zero (dedups diagonal region).
// ---------------------------------------------------------------------------
__global__ void __launch_bounds__(THREADS)
pack_kernel(const void* __restrict__ Araw, int n) {
    const int wpr = n >> 5;           // words per row
    const int gpr = wpr >> 2;         // 4-word groups per row
    const int groups = n * gpr;

    __shared__ int s_flag;
    if (threadIdx.x == 0) s_flag = 0;
    __syncthreads();
    {   // layout detect: int32 {0,1} layout has zero bytes at offsets %4 != 0
        const unsigned char* __restrict__ Ab = (const unsigned char*)Araw;
        int hit = 0;
        for (int k = threadIdx.x; k < 4096; k += blockDim.x)
            if ((k & 3) != 0 && Ab[k] != 0) hit = 1;
        if (hit) s_flag = 1;
    }
    __syncthreads();
    const bool bytelayout = (s_flag != 0);

    const int lane = threadIdx.x & 31;
    const int gw = (blockIdx.x * blockDim.x + threadIdx.x) >> 5;
    const int nw = (gridDim.x * blockDim.x) >> 5;

    if (!bytelayout) {
        const int* __restrict__ Ai = (const int*)Araw;
        for (int g = gw; g < groups; g += nw) {
            const int i  = g / gpr;
            const int wq = g - i * gpr;
            const int w0 = wq * 4;
            unsigned out[4];
            #pragma unroll
            for (int k = 0; k < 4; k++) {
                const int colbase = (w0 + k) << 5;
                unsigned bits = 0;
                if (colbase + 31 > i) {          // group word overlaps upper tri
                    const int col = colbase + lane;
                    const int val = Ai[(size_t)i * (size_t)n + col];
                    bits = __ballot_sync(0xffffffffu, (val != 0) && (col > i));
                }
                out[k] = bits;
            }
            if (lane == 0)
                *(uint4*)&g_bits[(size_t)i * wpr + w0] =
                    make_uint4(out[0], out[1], out[2], out[3]);
        }
    } else {
        const unsigned char* __restrict__ Ab = (const unsigned char*)Araw;
        for (int g = gw; g < groups; g += nw) {
            const int i  = g / gpr;
            const int wq = g - i * gpr;
            const int base = wq * 128;           // 128 cols per group
            unsigned w0 = 0, w1 = 0, w2 = 0, w3 = 0;
            if (base + 127 > i) {
                const int c0 = base + 4 * lane;
                uchar4 u = *(const uchar4*)(Ab + (size_t)i * (size_t)n + c0);
                unsigned nib =
                    ((u.x != 0 && c0     > i) ? 1u : 0u) |
                    ((u.y != 0 && c0 + 1 > i) ? 2u : 0u) |
                    ((u.z != 0 && c0 + 2 > i) ? 4u : 0u) |
                    ((u.w != 0 && c0 + 3 > i) ? 8u : 0u);
                unsigned v = nib << (4 * (lane & 7));
                v |= __shfl_xor_sync(0xffffffffu, v, 1);
                v |= __shfl_xor_sync(0xffffffffu, v, 2);
                v |= __shfl_xor_sync(0xffffffffu, v, 4);
                w0 = __shfl_sync(0xffffffffu, v, 0);
                w1 = __shfl_sync(0xffffffffu, v, 8);
                w2 = __shfl_sync(0xffffffffu, v, 16);
                w3 = __shfl_sync(0xffffffffu, v, 24);
            }
            if (lane == 0)
                *(uint4*)&g_bits[(size_t)i * wpr + wq * 4] =
                    make_uint4(w0, w1, w2, w3);
        }
    }
}

// ---------------------------------------------------------------------------
// main_kernel: quad work queue; masks from the packed bit matrix (L2-resident).
// Packed bits already exclude col <= row, so the loop needs no diagonal logic.
// ---------------------------------------------------------------------------
__global__ void __launch_bounds__(THREADS)
main_kernel(const float2* __restrict__ verts,
            const float2* __restrict__ gts,
            float* __restrict__ out,
            int n, int m) {
    __shared__ float sh[32];
    __shared__ int s_i0;
    const int t = threadIdx.x;
    const int B = blockDim.x;
    const int wpr = n >> 5;

    // ---- block 0: stats (r, gtr, gtperi) ----
    if (blockIdx.x == 0) {
        float ax = 0.f, ay = 0.f;
        for (int i = t; i < n; i += B) { float2 v = verts[i]; ax += v.x; ay += v.y; }
        float cx = block_sum256(ax, sh) / (float)n;
        float cy = block_sum256(ay, sh) / (float)n;

        float rs = 0.f;
        for (int i = t; i < n; i += B) {
            float2 v = verts[i];
            float dx = v.x - cx, dy = v.y - cy;
            rs += sqrtf(dx * dx + dy * dy);
        }
        float r = block_sum256(rs, sh) / (float)n;

        float gx = 0.f, gy = 0.f;
        for (int i = t; i < m; i += B) { float2 v = gts[i]; gx += v.x; gy += v.y; }
        float gcx = block_sum256(gx, sh) / (float)m;
        float gcy = block_sum256(gy, sh) / (float)m;

        float gs = 0.f, gp = 0.f;
        for (int i = t; i < m; i += B) {
            float2 v = gts[i];
            float dx = v.x - gcx, dy = v.y - gcy;
            gs += sqrtf(dx * dx + dy * dy);
            float2 w = gts[(i + 1 == m) ? 0 : (i + 1)];
            float ex = v.x - w.x, ey = v.y - w.y;
            gp += sqrtf(ex * ex + ey * ey);
        }
        float gtr    = block_sum256(gs, sh) / (float)m;
        float gtperi = block_sum256(gp, sh);

        if (t == 0) { g_r = r; g_gtr = gtr; g_gtperi = gtperi; }
    }

    const float4* __restrict__ v4 = (const float4*)verts;
    float acc[4] = {0.f, 0.f, 0.f, 0.f};

    for (;;) {
        if (t == 0) s_i0 = 4 * (int)atomicAdd(&g_state[2], 1ULL);
        __syncthreads();
        const int i0 = s_i0;
        __syncthreads();
        if (i0 >= n) break;

        float vx[4], vy[4];
        {
            float4 qa = v4[i0 >> 1];
            float4 qb = v4[(i0 >> 1) + 1];
            vx[0] = qa.x; vy[0] = qa.y; vx[1] = qa.z; vy[1] = qa.w;
            vx[2] = qb.x; vy[2] = qb.y; vx[3] = qb.z; vy[3] = qb.w;
        }

        const unsigned* __restrict__ b0 = g_bits + (size_t)(i0 + 0) * wpr;
        const unsigned* __restrict__ b1 = g_bits + (size_t)(i0 + 1) * wpr;
        const unsigned* __restrict__ b2 = g_bits + (size_t)(i0 + 2) * wpr;
        const unsigned* __restrict__ b3 = g_bits + (size_t)(i0 + 3) * wpr;

        const int c0 = (i0 + 1) & ~31;   // 32-aligned; sub-diagonal bits are 0

        #pragma unroll 2
        for (int c = c0 + 4 * t; c < n; c += 4 * B) {
            const int wi = c >> 5;
            const int sft = c & 31;      // multiple of 4
            unsigned nk[4];
            nk[0] = (b0[wi] >> sft) & 0xFu;
            nk[1] = (b1[wi] >> sft) & 0xFu;
            nk[2] = (b2[wi] >> sft) & 0xFu;
            nk[3] = (b3[wi] >> sft) & 0xFu;

            float4 pa = v4[c >> 1];
            float4 pb = v4[(c >> 1) + 1];
            float px[4] = {pa.x, pa.z, pb.x, pb.z};
            float py[4] = {pa.y, pa.w, pb.y, pb.w};

            #pragma unroll
            for (int k = 0; k < 4; k++) {
                float dx, dy, s;
                dx = px[0] - vx[k]; dy = py[0] - vy[k];
                s = fsqrt_fast(dx * dx + dy * dy); acc[k] += (nk[k] & 1u) ? s : 0.0f;
                dx = px[1] - vx[k]; dy = py[1] - vy[k];
                s = fsqrt_fast(dx * dx + dy * dy); acc[k] += (nk[k] & 2u) ? s : 0.0f;
                dx = px[2] - vx[k]; dy = py[2] - vy[k];
                s = fsqrt_fast(dx * dx + dy * dy); acc[k] += (nk[k] & 4u) ? s : 0.0f;
                dx = px[3] - vx[k]; dy = py[3] - vy[k];
                s = fsqrt_fast(dx * dx + dy * dy); acc[k] += (nk[k] & 8u) ? s : 0.0f;
            }
        }
    }

    float bsum = block_sum256((acc[0] + acc[1]) + (acc[2] + acc[3]), sh);

    if (t == 0) {
        atomicAdd((double*)&g_state[0], (double)bsum);
        __threadfence();
        unsigned long long prev = atomicAdd(&g_state[1], 1ULL);
        if (prev == (unsigned long long)(gridDim.x - 1)) {
            double peri_d = __longlong_as_double(
                (long long)atomicAdd(&g_state[0], 0ULL));
            float peri = (float)peri_d;
            float d1 = g_r - g_gtr;
            float d2 = peri - g_gtperi;
            out[0] = d1 * d1 + d2 * d2;
        }
    }
}

extern "C" void kernel_launch(void* const* d_in, const int* in_sizes, int n_in,
                              void* d_out, int out_size) {
    const float2* verts = (const float2*)d_in[0];
    const float2* gts   = (const float2*)d_in[1];
    const void*   A     = d_in[2];
    float* out = (float*)d_out;

    const int n = in_sizes[0] / 2;   // 8192
    const int m = in_sizes[1] / 2;   // 8192

    void* state_addr = nullptr;
    cudaGetSymbolAddress(&state_addr, g_state);
    cudaMemsetAsync(state_addr, 0, 3 * sizeof(unsigned long long));

    pack_kernel<<<PACK_BLOCKS, THREADS>>>(A, n);
    main_kernel<<<MAIN_BLOCKS, THREADS>>>(verts, gts, out, n, m);
}

// round 15
// speedup vs baseline: 3.1826x; 3.1826x over previous
#include <cuda_runtime.h>
#include <math.h>

#define GRID_BLOCKS 592
#define THREADS 256
#define NWARP 8
#define STAGES 3
#define WCOLS 128            // columns per warp-stage
#define SPAN (NWARP * WCOLS) // 1024: column stride between a warp's stages

// [0] peri accumulator (double bits), [1] done counter, [2] quad ticket
__device__ unsigned long long g_state[3];
__device__ float g_r, g_gtr, g_gtperi;

__device__ __forceinline__ float fsqrt_fast(float x) {
    float r;
    asm("sqrt.approx.f32 %0, %1;" : "=f"(r) : "f"(x));
    return r;
}

__device__ __forceinline__ float block_sum256(float v, float* sh) {
    const int t = threadIdx.x;
    for (int o = 16; o > 0; o >>= 1)
        v += __shfl_down_sync(0xffffffffu, v, o);
    if ((t & 31) == 0) sh[t >> 5] = v;
    __syncthreads();
    float r = 0.f;
    if (t < 32) {
        r = (t < 8) ? sh[t] : 0.f;
        for (int o = 4; o > 0; o >>= 1)
            r += __shfl_down_sync(0xffffffffu, r, o);
        if (t == 0) sh[0] = r;
    }
    __syncthreads();
    r = sh[0];
    __syncthreads();
    return r;
}

__device__ __forceinline__ unsigned smem_u32(const void* p) {
    return (unsigned)__cvta_generic_to_shared(p);
}
__device__ __forceinline__ void cp16(unsigned dst, const void* src) {
    asm volatile("cp.async.cg.shared.global [%0], [%1], 16;" :: "r"(dst), "l"(src));
}
__device__ __forceinline__ void cp_commit() { asm volatile("cp.async.commit_group;"); }
template <int N>
__device__ __forceinline__ void cp_wait() {
    asm volatile("cp.async.wait_group %0;" :: "n"(N) : "memory");
}

// sbuf[warp][stage][row][512B] — int32 uses 512B/row, byte layout first 128B
typedef unsigned char SBuf[STAGES][4][512];

template <bool BYTE>
__device__ __forceinline__ void stage_preload(
    const void* __restrict__ Araw, SBuf* sb, int n, int i0,
    int w, int lane, int wstart, int s) {
    const int col0 = wstart + s * SPAN;
    if (BYTE) {
        // 16 cols per 16B copy; lanes 0..7 cover 128 cols per row
        if (lane < 8) {
            const int col = col0 + 16 * lane;
            if (col < n) {
                const unsigned char* Ab = (const unsigned char*)Araw;
                #pragma unroll
                for (int k = 0; k < 4; k++)
                    cp16(smem_u32(&sb[w][s % STAGES][k][16 * lane]),
                         Ab + (size_t)(i0 + k) * (size_t)n + col);
            }
        }
    } else {
        const int col = col0 + 4 * lane;
        if (col < n) {
            const int* Ai = (const int*)Araw;
            #pragma unroll
            for (int k = 0; k < 4; k++)
                cp16(smem_u32(&sb[w][s % STAGES][k][16 * lane]),
                     Ai + (size_t)(i0 + k) * (size_t)n + col);
        }
    }
}

template <bool BYTE>
__device__ __forceinline__ void stage_compute(
    SBuf* sb, const float4* __restrict__ v4, int n,
    int w, int lane, int wstart, int s,
    const float* vx, const float* vy, float* acc) {
    const int col = wstart + s * SPAN + 4 * lane;
    if (col >= n) return;

    uint4 mk[4];
    if (BYTE) {
        #pragma unroll
        for (int k = 0; k < 4; k++) {
            uchar4 u = *(const uchar4*)&sb[w][s % STAGES][k][4 * lane];
            mk[k] = make_uint4(u.x, u.y, u.z, u.w);
        }
    } else {
        #pragma unroll
        for (int k = 0; k < 4; k++)
            mk[k] = *(const uint4*)&sb[w][s % STAGES][k][16 * lane];
    }

    float4 pa = v4[col >> 1];
    float4 pb = v4[(col >> 1) + 1];
    float px[4] = {pa.x, pa.z, pb.x, pb.z};
    float py[4] = {pa.y, pa.w, pb.y, pb.w};

    #pragma unroll
    for (int k = 0; k < 4; k++) {
        float dx, dy, sv;
        dx = px[0] - vx[k]; dy = py[0] - vy[k];
        sv = fsqrt_fast(dx * dx + dy * dy); acc[k] += mk[k].x ? sv : 0.0f;
        dx = px[1] - vx[k]; dy = py[1] - vy[k];
        sv = fsqrt_fast(dx * dx + dy * dy); acc[k] += mk[k].y ? sv : 0.0f;
        dx = px[2] - vx[k]; dy = py[2] - vy[k];
        sv = fsqrt_fast(dx * dx + dy * dy); acc[k] += mk[k].z ? sv : 0.0f;
        dx = px[3] - vx[k]; dy = py[3] - vy[k];
        sv = fsqrt_fast(dx * dx + dy * dy); acc[k] += mk[k].w ? sv : 0.0f;
    }
}

// ---------------------------------------------------------------------------
// Quad worker: warp-private 3-stage cp.async pipeline, NO block barriers
// in the steady state. Warp w covers columns {wstart + s*SPAN + [0,128)}.
// ---------------------------------------------------------------------------
template <bool BYTE>
__device__ __forceinline__ void quad_rows(
    const void* __restrict__ Araw, SBuf* sb,
    const float4* __restrict__ v4, int n, int i0, int t, float* acc) {
    const int w = t >> 5, lane = t & 31;

    float vx[4], vy[4];
    {
        float4 qa = v4[i0 >> 1];
        float4 qb = v4[(i0 >> 1) + 1];
        vx[0] = qa.x; vy[0] = qa.y; vx[1] = qa.z; vy[1] = qa.w;
        vx[2] = qb.x; vy[2] = qb.y; vx[3] = qb.z; vy[3] = qb.w;
    }

    // intra-quad pairs: (0,1)(0,2)(0,3)(1,2)(1,3)(2,3) -> threads 0..5
    if (t < 6) {
        int ii = (t < 3) ? 0 : ((t < 5) ? 1 : 2);
        int jj = (t < 3) ? (t + 1) : ((t < 5) ? (t - 1) : 3);
        size_t idx = (size_t)(i0 + ii) * (size_t)n + (i0 + jj);
        unsigned a = BYTE ? (unsigned)((const unsigned char*)Araw)[idx]
                          : (unsigned)((const int*)Araw)[idx];
        float dx = vx[jj] - vx[ii], dy = vy[jj] - vy[ii];
        float s = fsqrt_fast(dx * dx + dy * dy);
        acc[t & 3] += a ? s : 0.0f;
    }

    const int jstart = i0 + 4;
    const int wstart = jstart + WCOLS * w;
    const int nst = (n > wstart) ? (n - wstart + SPAN - 1) / SPAN : 0;

    // prefill STAGES-1 stages (commit a group each, possibly empty)
    #pragma unroll
    for (int s = 0; s < STAGES - 1; s++) {
        if (s < nst) stage_preload<BYTE>(Araw, sb, n, i0, w, lane, wstart, s);
        cp_commit();
    }

    for (int s = 0; s < nst; s++) {
        if (s + STAGES - 1 < nst)
            stage_preload<BYTE>(Araw, sb, n, i0, w, lane, wstart, s + STAGES - 1);
        cp_commit();
        cp_wait<STAGES - 1>();   // stage s landed
        stage_compute<BYTE>(sb, v4, n, w, lane, wstart, s, vx, vy, acc);
    }
    cp_wait<0>();                // drain before buffers are reused next quad
}

__global__ void __launch_bounds__(THREADS)
fused_kernel(const float2* __restrict__ verts,
             const float2* __restrict__ gts,
             const void* __restrict__ Araw,
             float* __restrict__ out,
             int n, int m) {
    extern __shared__ unsigned char dynsmem[];   // 48 KB staging
    SBuf* sbuf = (SBuf*)dynsmem;
    __shared__ float sh[32];
    __shared__ int s_misc;
    const int t = threadIdx.x;
    const int B = blockDim.x;

    // ---- layout detect: int32 {0,1} layout has zero bytes at offsets %4!=0 ----
    if (t == 0) s_misc = 0;
    __syncthreads();
    {
        const unsigned char* __restrict__ Ab = (const unsigned char*)Araw;
        int hit = 0;
        for (int k = t; k < 4096; k += B)
            if ((k & 3) != 0 && Ab[k] != 0) hit = 1;
        if (hit) s_misc = 1;
    }
    __syncthreads();
    const bool bytelayout = (s_misc != 0);
    __syncthreads();

    // ---- block 0: stats (r, gtr, gtperi) ----
    if (blockIdx.x == 0) {
        float ax = 0.f, ay = 0.f;
        for (int i = t; i < n; i += B) { float2 v = verts[i]; ax += v.x; ay += v.y; }
        float cx = block_sum256(ax, sh) / (float)n;
        float cy = block_sum256(ay, sh) / (float)n;

        float rs = 0.f;
        for (int i = t; i < n; i += B) {
            float2 v = verts[i];
            float dx = v.x - cx, dy = v.y - cy;
            rs += sqrtf(dx * dx + dy * dy);
        }
        float r = block_sum256(rs, sh) / (float)n;

        float gx = 0.f, gy = 0.f;
        for (int i = t; i < m; i += B) { float2 v = gts[i]; gx += v.x; gy += v.y; }
        float gcx = block_sum256(gx, sh) / (float)m;
        float gcy = block_sum256(gy, sh) / (float)m;

        float gs = 0.f, gp = 0.f;
        for (int i = t; i < m; i += B) {
            float2 v = gts[i];
            float dx = v.x - gcx, dy = v.y - gcy;
            gs += sqrtf(dx * dx + dy * dy);
            float2 w = gts[(i + 1 == m) ? 0 : (i + 1)];
            float ex = v.x - w.x, ey = v.y - w.y;
            gp += sqrtf(ex * ex + ey * ey);
        }
        float gtr    = block_sum256(gs, sh) / (float)m;
        float gtperi = block_sum256(gp, sh);

        if (t == 0) { g_r = r; g_gtr = gtr; g_gtperi = gtperi; }
    }

    // ---- pair-perimeter: row quads via work-stealing queue ----
    const float4* __restrict__ v4 = (const float4*)verts;
    float acc[4] = {0.f, 0.f, 0.f, 0.f};

    for (;;) {
        __syncthreads();         // all warps drained; buffers + ticket reusable
        if (t == 0)
            s_misc = 4 * (int)atomicAdd(&g_state[2], 1ULL);
        __syncthreads();
        const int i0 = s_misc;
        if (i0 >= n) break;

        if (bytelayout)
            quad_rows<true>(Araw, sbuf, v4, n, i0, t, acc);
        else
            quad_rows<false>(Araw, sbuf, v4, n, i0, t, acc);
    }

    // ---- block reduction + global accumulate + last-block finalize ----
    float bsum = block_sum256((acc[0] + acc[1]) + (acc[2] + acc[3]), sh);

    if (t == 0) {
        atomicAdd((double*)&g_state[0], (double)bsum);
        __threadfence();
        unsigned long long prev = atomicAdd(&g_state[1], 1ULL);
        if (prev == (unsigned long long)(gridDim.x - 1)) {
            double peri_d = __longlong_as_double(
                (long long)atomicAdd(&g_state[0], 0ULL));
            float peri = (float)peri_d;
            float d1 = g_r - g_gtr;
            float d2 = peri - g_gtperi;
            out[0] = d1 * d1 + d2 * d2;
        }
    }
}

extern "C" void kernel_launch(void* const* d_in, const int* in_sizes, int n_in,
                              void* d_out, int out_size) {
    const float2* verts = (const float2*)d_in[0];
    const float2* gts   = (const float2*)d_in[1];
    const void*   A     = d_in[2];
    float* out = (float*)d_out;

    const int n = in_sizes[0] / 2;   // 8192
    const int m = in_sizes[1] / 2;   // 8192

    void* state_addr = nullptr;
    cudaGetSymbolAddress(&state_addr, g_state);
    cudaMemsetAsync(state_addr, 0, 3 * sizeof(unsigned long long));

    const size_t smem = sizeof(SBuf) * NWARP;   // 48 KB
    cudaFuncSetAttribute(fused_kernel,
                         cudaFuncAttributeMaxDynamicSharedMemorySize,
                         (int)smem);

    fused_kernel<<<GRID_BLOCKS, THREADS, smem>>>(verts, gts, A, out, n, m);
}

// round 16
// speedup vs baseline: 4.0718x; 1.2794x over previous
#include <cuda_runtime.h>
#include <math.h>

#define GRID_BLOCKS 888
#define THREADS 256
#define VB 2                 // batches of 4 pairs per row per iteration

// [0] peri accumulator (double bits), [1] done counter, [2] row-pair ticket
__device__ unsigned long long g_state[3];
__device__ float g_r, g_gtr, g_gtperi;

__device__ __forceinline__ float fsqrt_fast(float x) {
    float r;
    asm("sqrt.approx.f32 %0, %1;" : "=f"(r) : "f"(x));
    return r;
}

__device__ __forceinline__ void pf_l2(const void* p) {
    asm volatile("prefetch.global.L2 [%0];" :: "l"(p));
}

__device__ __forceinline__ float block_sum256(float v, float* sh) {
    const int t = threadIdx.x;
    for (int o = 16; o > 0; o >>= 1)
        v += __shfl_down_sync(0xffffffffu, v, o);
    if ((t & 31) == 0) sh[t >> 5] = v;
    __syncthreads();
    float r = 0.f;
    if (t < 32) {
        r = (t < 8) ? sh[t] : 0.f;
        for (int o = 4; o > 0; o >>= 1)
            r += __shfl_down_sync(0xffffffffu, r, o);
        if (t == 0) sh[0] = r;
    }
    __syncthreads();
    r = sh[0];
    __syncthreads();
    return r;
}

// ---------------------------------------------------------------------------
// Fused kernel (R8 structure + L2 prefetch of the mask stream + __ldcs).
// Row pairs via work queue; main loop unchecked (n % 4 == 0, aligned tiles).
// ---------------------------------------------------------------------------
__global__ void __launch_bounds__(THREADS)
fused_kernel(const float2* __restrict__ verts,
             const float2* __restrict__ gts,
             const void* __restrict__ Araw,
             float* __restrict__ out,
             int n, int m) {
    __shared__ float sh[32];
    __shared__ int s_misc;
    const int t = threadIdx.x;
    const int B = blockDim.x;

    // ---- layout detect: int32 {0,1} layout has zero bytes at offsets %4!=0 ----
    if (t == 0) s_misc = 0;
    __syncthreads();
    {
        const unsigned char* __restrict__ Ab = (const unsigned char*)Araw;
        int hit = 0;
        for (int k = t; k < 4096; k += B)
            if ((k & 3) != 0 && Ab[k] != 0) hit = 1;
        if (hit) s_misc = 1;
    }
    __syncthreads();
    const bool bytelayout = (s_misc != 0);
    __syncthreads();

    // ---- block 0: stats (r, gtr, gtperi) ----
    if (blockIdx.x == 0) {
        float ax = 0.f, ay = 0.f;
        for (int i = t; i < n; i += B) { float2 v = verts[i]; ax += v.x; ay += v.y; }
        float cx = block_sum256(ax, sh) / (float)n;
        float cy = block_sum256(ay, sh) / (float)n;

        float rs = 0.f;
        for (int i = t; i < n; i += B) {
            float2 v = verts[i];
            float dx = v.x - cx, dy = v.y - cy;
            rs += sqrtf(dx * dx + dy * dy);
        }
        float r = block_sum256(rs, sh) / (float)n;

        float gx = 0.f, gy = 0.f;
        for (int i = t; i < m; i += B) { float2 v = gts[i]; gx += v.x; gy += v.y; }
        float gcx = block_sum256(gx, sh) / (float)m;
        float gcy = block_sum256(gy, sh) / (float)m;

        float gs = 0.f, gp = 0.f;
        for (int i = t; i < m; i += B) {
            float2 v = gts[i];
            float dx = v.x - gcx, dy = v.y - gcy;
            gs += sqrtf(dx * dx + dy * dy);
            float2 w = gts[(i + 1 == m) ? 0 : (i + 1)];
            float ex = v.x - w.x, ey = v.y - w.y;
            gp += sqrtf(ex * ex + ey * ey);
        }
        float gtr    = block_sum256(gs, sh) / (float)m;
        float gtperi = block_sum256(gp, sh);

        if (t == 0) { g_r = r; g_gtr = gtr; g_gtperi = gtperi; }
    }

    // ---- pair-perimeter: row pairs via work-stealing queue ----
    const float4* __restrict__ v4 = (const float4*)verts;  // 2 verts per float4
    float s00 = 0.f, s01 = 0.f, s10 = 0.f, s11 = 0.f;

    for (;;) {
        if (t == 0)
            s_misc = 2 * (int)atomicAdd(&g_state[2], 1ULL);
        __syncthreads();
        const int i0 = s_misc;
        __syncthreads();
        if (i0 >= n) break;
        const int i1 = i0 + 1;            // n even => i1 < n

        const float2 va = verts[i0];
        const float2 vb = verts[i1];
        const float vix0 = va.x, viy0 = va.y;
        const float vix1 = vb.x, viy1 = vb.y;

        const size_t base0 = (size_t)i0 * (size_t)n;
        const size_t base1 = (size_t)i1 * (size_t)n;

        // pair (i0, i1) belongs only to row i0
        if (t == 0) {
            unsigned int a;
            if (bytelayout) a = ((const unsigned char*)Araw)[base0 + i1];
            else            a = (unsigned int)((const int*)Araw)[base0 + i1];
            float dx = vix1 - vix0, dy = viy1 - viy0;
            float s = fsqrt_fast(dx * dx + dy * dy);
            s00 += a ? s : 0.0f;
        }

        const int jstart = i1 + 1;
        const int j4start = (jstart + 3) & ~3;
        const int npro = j4start - jstart;

        if (t < npro) {
            int j = jstart + t;
            if (j < n) {
                unsigned int a0, a1;
                if (bytelayout) {
                    a0 = ((const unsigned char*)Araw)[base0 + j];
                    a1 = ((const unsigned char*)Araw)[base1 + j];
                } else {
                    a0 = (unsigned int)((const int*)Araw)[base0 + j];
                    a1 = (unsigned int)((const int*)Araw)[base1 + j];
                }
                float2 p = verts[j];
                float dx0 = p.x - vix0, dy0 = p.y - viy0;
                float dx1 = p.x - vix1, dy1 = p.y - viy1;
                float d0 = fsqrt_fast(dx0 * dx0 + dy0 * dy0);
                float d1 = fsqrt_fast(dx1 * dx1 + dy1 * dy1);
                s00 += a0 ? d0 : 0.0f;
                s10 += a1 ? d1 : 0.0f;
            }
        }

        const int STRIDE = VB * 4 * B;    // ints/bytes per thread per iteration

        if (bytelayout) {
            const unsigned char* __restrict__ row0 = (const unsigned char*)Araw + base0;
            const unsigned char* __restrict__ row1 = (const unsigned char*)Araw + base1;
            int jb = j4start + 4 * t;
            for (; jb + 4 * B < n; jb += STRIDE) {
                uchar4 a0[VB], a1[VB]; float4 pa[VB], pb[VB];
                #pragma unroll
                for (int u = 0; u < VB; u++) {
                    int js = jb + u * 4 * B;
                    a0[u] = __ldcs((const uchar4*)(row0 + js));
                    a1[u] = __ldcs((const uchar4*)(row1 + js));
                    pa[u] = v4[js >> 1];
                    pb[u] = v4[(js >> 1) + 1];
                }
                // prefetch next iteration's mask lines (1 lane per 128B line)
                if ((t & 31) == 0) {
                    int jpf = jb + STRIDE;
                    if (jpf < n) { pf_l2(row0 + jpf); pf_l2(row1 + jpf); }
                }
                #pragma unroll
                for (int u = 0; u < VB; u++) {
                    float dx, dy, s;
                    dx = pa[u].x - vix0; dy = pa[u].y - viy0;
                    s = fsqrt_fast(dx*dx + dy*dy); s00 += a0[u].x ? s : 0.0f;
                    dx = pa[u].x - vix1; dy = pa[u].y - viy1;
                    s = fsqrt_fast(dx*dx + dy*dy); s10 += a1[u].x ? s : 0.0f;
                    dx = pa[u].z - vix0; dy = pa[u].w - viy0;
                    s = fsqrt_fast(dx*dx + dy*dy); s01 += a0[u].y ? s : 0.0f;
                    dx = pa[u].z - vix1; dy = pa[u].w - viy1;
                    s = fsqrt_fast(dx*dx + dy*dy); s11 += a1[u].y ? s : 0.0f;
                    dx = pb[u].x - vix0; dy = pb[u].y - viy0;
                    s = fsqrt_fast(dx*dx + dy*dy); s00 += a0[u].z ? s : 0.0f;
                    dx = pb[u].x - vix1; dy = pb[u].y - viy1;
                    s = fsqrt_fast(dx*dx + dy*dy); s10 += a1[u].z ? s : 0.0f;
                    dx = pb[u].z - vix0; dy = pb[u].w - viy0;
                    s = fsqrt_fast(dx*dx + dy*dy); s01 += a0[u].w ? s : 0.0f;
                    dx = pb[u].z - vix1; dy = pb[u].w - viy1;
                    s = fsqrt_fast(dx*dx + dy*dy); s11 += a1[u].w ? s : 0.0f;
                }
            }
            for (; jb < n; jb += 4 * B) {
                uchar4 a0 = __ldcs((const uchar4*)(row0 + jb));
                uchar4 a1 = __ldcs((const uchar4*)(row1 + jb));
                float4 pa = v4[jb >> 1];
                float4 pb = v4[(jb >> 1) + 1];
                float dx, dy, s;
                dx = pa.x - vix0; dy = pa.y - viy0;
                s = fsqrt_fast(dx*dx + dy*dy); s00 += a0.x ? s : 0.0f;
                dx = pa.x - vix1; dy = pa.y - viy1;
                s = fsqrt_fast(dx*dx + dy*dy); s10 += a1.x ? s : 0.0f;
                dx = pa.z - vix0; dy = pa.w - viy0;
                s = fsqrt_fast(dx*dx + dy*dy); s01 += a0.y ? s : 0.0f;
                dx = pa.z - vix1; dy = pa.w - viy1;
                s = fsqrt_fast(dx*dx + dy*dy); s11 += a1.y ? s : 0.0f;
                dx = pb.x - vix0; dy = pb.y - viy0;
                s = fsqrt_fast(dx*dx + dy*dy); s00 += a0.z ? s : 0.0f;
                dx = pb.x - vix1; dy = pb.y - viy1;
                s = fsqrt_fast(dx*dx + dy*dy); s10 += a1.z ? s : 0.0f;
                dx = pb.z - vix0; dy = pb.w - viy0;
                s = fsqrt_fast(dx*dx + dy*dy); s01 += a0.w ? s : 0.0f;
                dx = pb.z - vix1; dy = pb.w - viy1;
                s = fsqrt_fast(dx*dx + dy*dy); s11 += a1.w ? s : 0.0f;
            }
        } else {
            const int* __restrict__ row0 = (const int*)Araw + base0;
            const int* __restrict__ row1 = (const int*)Araw + base1;
            int jb = j4start + 4 * t;
            for (; jb + 4 * B < n; jb += STRIDE) {
                int4 a0[VB], a1[VB]; float4 pa[VB], pb[VB];
                #pragma unroll
                for (int u = 0; u < VB; u++) {
                    int js = jb + u * 4 * B;
                    a0[u] = __ldcs((const int4*)(row0 + js));
                    a1[u] = __ldcs((const int4*)(row1 + js));
                    pa[u] = v4[js >> 1];
                    pb[u] = v4[(js >> 1) + 1];
                }
                // prefetch next iteration's mask lines (1 lane per 128B line)
                if ((t & 7) == 0) {
                    int jpf = jb + STRIDE;
                    if (jpf < n) { pf_l2(row0 + jpf); pf_l2(row1 + jpf); }
                }
                #pragma unroll
                for (int u = 0; u < VB; u++) {
                    float dx, dy, s;
                    dx = pa[u].x - vix0; dy = pa[u].y - viy0;
                    s = fsqrt_fast(dx*dx + dy*dy); s00 += a0[u].x ? s : 0.0f;
                    dx = pa[u].x - vix1; dy = pa[u].y - viy1;
                    s = fsqrt_fast(dx*dx + dy*dy); s10 += a1[u].x ? s : 0.0f;
                    dx = pa[u].z - vix0; dy = pa[u].w - viy0;
                    s = fsqrt_fast(dx*dx + dy*dy); s01 += a0[u].y ? s : 0.0f;
                    dx = pa[u].z - vix1; dy = pa[u].w - viy1;
                    s = fsqrt_fast(dx*dx + dy*dy); s11 += a1[u].y ? s : 0.0f;
                    dx = pb[u].x - vix0; dy = pb[u].y - viy0;
                    s = fsqrt_fast(dx*dx + dy*dy); s00 += a0[u].z ? s : 0.0f;
                    dx = pb[u].x - vix1; dy = pb[u].y - viy1;
                    s = fsqrt_fast(dx*dx + dy*dy); s10 += a1[u].z ? s : 0.0f;
                    dx = pb[u].z - vix0; dy = pb[u].w - viy0;
                    s = fsqrt_fast(dx*dx + dy*dy); s01 += a0[u].w ? s : 0.0f;
                    dx = pb[u].z - vix1; dy = pb[u].w - viy1;
                    s = fsqrt_fast(dx*dx + dy*dy); s11 += a1[u].w ? s : 0.0f;
                }
            }
            for (; jb < n; jb += 4 * B) {
                int4 a0 = __ldcs((const int4*)(row0 + jb));
                int4 a1 = __ldcs((const int4*)(row1 + jb));
                float4 pa = v4[jb >> 1];
                float4 pb = v4[(jb >> 1) + 1];
                float dx, dy, s;
                dx = pa.x - vix0; dy = pa.y - viy0;
                s = fsqrt_fast(dx*dx + dy*dy); s00 += a0.x ? s : 0.0f;
                dx = pa.x - vix1; dy = pa.y - viy1;
                s = fsqrt_fast(dx*dx + dy*dy); s10 += a1.x ? s : 0.0f;
                dx = pa.z - vix0; dy = pa.w - viy0;
                s = fsqrt_fast(dx*dx + dy*dy); s01 += a0.y ? s : 0.0f;
                dx = pa.z - vix1; dy = pa.w - viy1;
                s = fsqrt_fast(dx*dx + dy*dy); s11 += a1.y ? s : 0.0f;
                dx = pb.x - vix0; dy = pb.y - viy0;
                s = fsqrt_fast(dx*dx + dy*dy); s00 += a0.z ? s : 0.0f;
                dx = pb.x - vix1; dy = pb.y - viy1;
                s = fsqrt_fast(dx*dx + dy*dy); s10 += a1.z ? s : 0.0f;
                dx = pb.z - vix0; dy = pb.w - viy0;
                s = fsqrt_fast(dx*dx + dy*dy); s01 += a0.w ? s : 0.0f;
                dx = pb.z - vix1; dy = pb.w - viy1;
                s = fsqrt_fast(dx*dx + dy*dy); s11 += a1.w ? s : 0.0f;
            }
        }
    }

    // ---- block reduction + global accumulate + last-block finalize ----
    float bsum = block_sum256((s00 + s01) + (s10 + s11), sh);

    if (t == 0) {
        atomicAdd((double*)&g_state[0], (double)bsum);
        __threadfence();
        unsigned long long prev = atomicAdd(&g_state[1], 1ULL);
        if (prev == (unsigned long long)(gridDim.x - 1)) {
            double peri_d = __longlong_as_double(
                (long long)atomicAdd(&g_state[0], 0ULL));
            float peri = (float)peri_d;
            float d1 = g_r - g_gtr;
            float d2 = peri - g_gtperi;
            out[0] = d1 * d1 + d2 * d2;
        }
    }
}

extern "C" void kernel_launch(void* const* d_in, const int* in_sizes, int n_in,
                              void* d_out, int out_size) {
    const float2* verts = (const float2*)d_in[0];
    const float2* gts   = (const float2*)d_in[1];
    const void*   A     = d_in[2];
    float* out = (float*)d_out;

    const int n = in_sizes[0] / 2;   // 8192
    const int m = in_sizes[1] / 2;   // 8192

    void* state_addr = nullptr;
    cudaGetSymbolAddress(&state_addr, g_state);
    cudaMemsetAsync(state_addr, 0, 3 * sizeof(unsigned long long));

    fused_kernel<<<GRID_BLOCKS, THREADS>>>(verts, gts, A, out, n, m);
}

// round 17
// speedup vs baseline: 4.4914x; 1.1031x over previous
#include <cuda_runtime.h>
#include <math.h>

#define GRID_BLOCKS 888
#define THREADS 256

// [0] peri accumulator (double bits), [1] done counter, [2] quad ticket
__device__ unsigned long long g_state[3];
__device__ float g_r, g_gtr, g_gtperi;

__device__ __forceinline__ float fsqrt_fast(float x) {
    float r;
    asm("sqrt.approx.f32 %0, %1;" : "=f"(r) : "f"(x));
    return r;
}
__device__ __forceinline__ void pf_l2(const void* p) {
    asm volatile("prefetch.global.L2 [%0];" :: "l"(p));
}

__device__ __forceinline__ float block_sum256(float v, float* sh) {
    const int t = threadIdx.x;
    for (int o = 16; o > 0; o >>= 1)
        v += __shfl_down_sync(0xffffffffu, v, o);
    if ((t & 31) == 0) sh[t >> 5] = v;
    __syncthreads();
    float r = 0.f;
    if (t < 32) {
        r = (t < 8) ? sh[t] : 0.f;
        for (int o = 4; o > 0; o >>= 1)
            r += __shfl_down_sync(0xffffffffu, r, o);
        if (t == 0) sh[0] = r;
    }
    __syncthreads();
    r = sh[0];
    __syncthreads();
    return r;
}

// streaming mask loads (evict-first; A bytes are consumed exactly once)
__device__ __forceinline__ uint4 load_mask4(const int* row, int jb) {
    int4 a = __ldcs((const int4*)(row + jb));
    return make_uint4((unsigned)a.x, (unsigned)a.y, (unsigned)a.z, (unsigned)a.w);
}
__device__ __forceinline__ uint4 load_mask4(const unsigned char* row, int jb) {
    uchar4 a = __ldcs((const uchar4*)(row + jb));
    return make_uint4(a.x, a.y, a.z, a.w);
}
__device__ __forceinline__ unsigned load_mask1(const int* A, size_t idx) {
    return (unsigned)A[idx];
}
__device__ __forceinline__ unsigned load_mask1(const unsigned char* A, size_t idx) {
    return (unsigned)A[idx];
}

// ---------------------------------------------------------------------------
// Quad worker: rows i0..i0+3 share vertex loads; unchecked main loop
// (jstart = i0+4 is 4-aligned, n % 4 == 0); L2 prefetch 2 iterations ahead.
// ---------------------------------------------------------------------------
template <typename ET, int PFLANE>
__device__ __forceinline__ void quad_rows(const ET* __restrict__ A,
                                          const float4* __restrict__ v4,
                                          int n, int i0, int t, int B,
                                          float* acc) {
    float vx[4], vy[4];
    {
        float4 qa = v4[i0 >> 1];
        float4 qb = v4[(i0 >> 1) + 1];
        vx[0] = qa.x; vy[0] = qa.y; vx[1] = qa.z; vy[1] = qa.w;
        vx[2] = qb.x; vy[2] = qb.y; vx[3] = qb.z; vy[3] = qb.w;
    }

    // intra-quad pairs: (0,1)(0,2)(0,3)(1,2)(1,3)(2,3) -> threads 0..5
    if (t < 6) {
        int ii = (t < 3) ? 0 : ((t < 5) ? 1 : 2);
        int jj = (t < 3) ? (t + 1) : ((t < 5) ? (t - 1) : 3);
        unsigned a = load_mask1(A, (size_t)(i0 + ii) * (size_t)n + (i0 + jj));
        float dx = vx[jj] - vx[ii], dy = vy[jj] - vy[ii];
        float s = fsqrt_fast(dx * dx + dy * dy);
        acc[t & 3] += a ? s : 0.0f;
    }

    const ET* __restrict__ r0 = A + (size_t)(i0 + 0) * (size_t)n;
    const ET* __restrict__ r1 = A + (size_t)(i0 + 1) * (size_t)n;
    const ET* __restrict__ r2 = A + (size_t)(i0 + 2) * (size_t)n;
    const ET* __restrict__ r3 = A + (size_t)(i0 + 3) * (size_t)n;

    const int jstart = i0 + 4;
    const int STRIDE = 4 * B;                 // columns per iteration

    for (int jb = jstart + 4 * t; jb < n; jb += STRIDE) {
        uint4 m0 = load_mask4(r0, jb);
        uint4 m1 = load_mask4(r1, jb);
        uint4 m2 = load_mask4(r2, jb);
        uint4 m3 = load_mask4(r3, jb);
        float4 pa = v4[jb >> 1];
        float4 pb = v4[(jb >> 1) + 1];

        // prefetch 2 iterations ahead: one lane per 128B line per row
        if ((t & PFLANE) == 0) {
            int jpf = jb + 2 * STRIDE;
            if (jpf < n) {
                pf_l2(r0 + jpf); pf_l2(r1 + jpf);
                pf_l2(r2 + jpf); pf_l2(r3 + jpf);
            }
        }

        float px[4] = {pa.x, pa.z, pb.x, pb.z};
        float py[4] = {pa.y, pa.w, pb.y, pb.w};
        uint4 mk[4] = {m0, m1, m2, m3};

        #pragma unroll
        for (int r = 0; r < 4; r++) {
            float dx, dy, s;
            dx = px[0] - vx[r]; dy = py[0] - vy[r];
            s = fsqrt_fast(dx * dx + dy * dy); acc[r] += mk[r].x ? s : 0.0f;
            dx = px[1] - vx[r]; dy = py[1] - vy[r];
            s = fsqrt_fast(dx * dx + dy * dy); acc[r] += mk[r].y ? s : 0.0f;
            dx = px[2] - vx[r]; dy = py[2] - vy[r];
            s = fsqrt_fast(dx * dx + dy * dy); acc[r] += mk[r].z ? s : 0.0f;
            dx = px[3] - vx[r]; dy = py[3] - vy[r];
            s = fsqrt_fast(dx * dx + dy * dy); acc[r] += mk[r].w ? s : 0.0f;
        }
    }
}

__global__ void __launch_bounds__(THREADS)
fused_kernel(const float2* __restrict__ verts,
             const float2* __restrict__ gts,
             const void* __restrict__ Araw,
             float* __restrict__ out,
             int n, int m) {
    __shared__ float sh[32];
    __shared__ int s_misc;
    const int t = threadIdx.x;
    const int B = blockDim.x;

    // ---- layout detect: int32 {0,1} layout has zero bytes at offsets %4!=0 ----
    if (t == 0) s_misc = 0;
    __syncthreads();
    {
        const unsigned char* __restrict__ Ab = (const unsigned char*)Araw;
        int hit = 0;
        for (int k = t; k < 4096; k += B)
            if ((k & 3) != 0 && Ab[k] != 0) hit = 1;
        if (hit) s_misc = 1;
    }
    __syncthreads();
    const bool bytelayout = (s_misc != 0);
    __syncthreads();

    // ---- block 0: stats (r, gtr, gtperi) ----
    if (blockIdx.x == 0) {
        float ax = 0.f, ay = 0.f;
        for (int i = t; i < n; i += B) { float2 v = verts[i]; ax += v.x; ay += v.y; }
        float cx = block_sum256(ax, sh) / (float)n;
        float cy = block_sum256(ay, sh) / (float)n;

        float rs = 0.f;
        for (int i = t; i < n; i += B) {
            float2 v = verts[i];
            float dx = v.x - cx, dy = v.y - cy;
            rs += sqrtf(dx * dx + dy * dy);
        }
        float r = block_sum256(rs, sh) / (float)n;

        float gx = 0.f, gy = 0.f;
        for (int i = t; i < m; i += B) { float2 v = gts[i]; gx += v.x; gy += v.y; }
        float gcx = block_sum256(gx, sh) / (float)m;
        float gcy = block_sum256(gy, sh) / (float)m;

        float gs = 0.f, gp = 0.f;
        for (int i = t; i < m; i += B) {
            float2 v = gts[i];
            float dx = v.x - gcx, dy = v.y - gcy;
            gs += sqrtf(dx * dx + dy * dy);
            float2 w = gts[(i + 1 == m) ? 0 : (i + 1)];
            float ex = v.x - w.x, ey = v.y - w.y;
            gp += sqrtf(ex * ex + ey * ey);
        }
        float gtr    = block_sum256(gs, sh) / (float)m;
        float gtperi = block_sum256(gp, sh);

        if (t == 0) { g_r = r; g_gtr = gtr; g_gtperi = gtperi; }
    }

    // ---- pair-perimeter: row quads via work-stealing queue ----
    const float4* __restrict__ v4 = (const float4*)verts;
    float acc[4] = {0.f, 0.f, 0.f, 0.f};

    for (;;) {
        if (t == 0)
            s_misc = 4 * (int)atomicAdd(&g_state[2], 1ULL);
        __syncthreads();
        const int i0 = s_misc;
        __syncthreads();
        if (i0 >= n) break;

        if (bytelayout)
            // byte path: 4 cols/thread = 1KB/row/iter; 1 pf-lane per 32 threads
            quad_rows<unsigned char, 31>((const unsigned char*)Araw, v4,
                                         n, i0, t, B, acc);
        else
            // int path: 4 cols/thread = 4KB/row/iter; 1 pf-lane per 8 threads
            quad_rows<int, 7>((const int*)Araw, v4, n, i0, t, B, acc);
    }

    // ---- block reduction + global accumulate + last-block finalize ----
    float bsum = block_sum256((acc[0] + acc[1]) + (acc[2] + acc[3]), sh);

    if (t == 0) {
        atomicAdd((double*)&g_state[0], (double)bsum);
        __threadfence();
        unsigned long long prev = atomicAdd(&g_state[1], 1ULL);
        if (prev == (unsigned long long)(gridDim.x - 1)) {
            double peri_d = __longlong_as_double(
                (long long)atomicAdd(&g_state[0], 0ULL));
            float peri = (float)peri_d;
            float d1 = g_r - g_gtr;
            float d2 = peri - g_gtperi;
            out[0] = d1 * d1 + d2 * d2;
        }
    }
}

extern "C" void kernel_launch(void* const* d_in, const int* in_sizes, int n_in,
                              void* d_out, int out_size) {
    const float2* verts = (const float2*)d_in[0];
    const float2* gts   = (const float2*)d_in[1];
    const void*   A     = d_in[2];
    float* out = (float*)d_out;

    const int n = in_sizes[0] / 2;   // 8192
    const int m = in_sizes[1] / 2;   // 8192

    void* state_addr = nullptr;
    cudaGetSymbolAddress(&state_addr, g_state);
    cudaMemsetAsync(state_addr, 0, 3 * sizeof(unsigned long long));

    fused_kernel<<<GRID_BLOCKS, THREADS>>>(verts, gts, A, out, n, m);
}